// round 11
// baseline (speedup 1.0000x reference)
#include <cuda_runtime.h>
#include <cstdint>
#include <cstddef>

// Problem constants
#define BATCH   16
#define CIN     256
#define HH      64
#define WW      64
#define HW      4096
#define OC_QKV  768
#define HEADS   64
#define ATT_CH  512
#define OC_OUT  256
#define K_PROJ  512

// ---------------------------------------------------------------------------
// Paired layout (A operands + GEMM1 B), 16-k chunks, 32 floats/chunk:
//   off(kk) = (kk/8)*16 + (kk%4)*4 + ((kk%8)/4)*2 ; hi at off, lo at off+1
// Hi-only layout (GEMM2 B), 16 floats/chunk:
//   off(kk) = (kk/8)*8 + (kk%4)*2 + ((kk%8)/4)
// ---------------------------------------------------------------------------
__device__ float g_qkv [(size_t)BATCH * OC_QKV * HW];
__device__ float g_agg [(size_t)BATCH * OC_QKV * HW];
__device__ float g_kv  [(size_t)BATCH * HEADS * 4 * 72];
__device__ float g_attp[(size_t)BATCH * HW * ATT_CH];    // hi-only [b][n][512]
__device__ float g_xtp [(size_t)BATCH * HW * 2 * CIN];   // paired  [b][n][16][32]
__device__ float g_wqp [(size_t)OC_QKV * 2 * CIN];
__device__ float g_wpp [(size_t)OC_OUT * 2 * K_PROJ];

// ---------------------------------------------------------------------------
// Helpers
// ---------------------------------------------------------------------------
__device__ __forceinline__ float tf32r(float x) {
    float r;
    asm("cvt.rna.tf32.f32 %0, %1;" : "=f"(r) : "f"(x));
    return r;
}
__device__ __forceinline__ int pair16(int kk) {
    return ((kk >> 3) << 4) + ((kk & 3) << 2) + (((kk >> 2) & 1) << 1);
}
__device__ __forceinline__ void mma_tf32(float* d, const uint32_t* a, const uint32_t* b) {
    asm volatile(
        "mma.sync.aligned.m16n8k8.row.col.f32.tf32.tf32.f32 "
        "{%0,%1,%2,%3}, {%4,%5,%6,%7}, {%8,%9}, {%0,%1,%2,%3};"
        : "+f"(d[0]), "+f"(d[1]), "+f"(d[2]), "+f"(d[3])
        : "r"(a[0]), "r"(a[1]), "r"(a[2]), "r"(a[3]), "r"(b[0]), "r"(b[1]));
}
#define CP_ASYNC16(sa, gp) \
    asm volatile("cp.async.ca.shared.global [%0], [%1], 16;" :: "r"(sa), "l"(gp))
#define CP_COMMIT() asm volatile("cp.async.commit_group;")
#define CP_WAIT_ALL() asm volatile("cp.async.wait_group 0;")

// ---------------------------------------------------------------------------
// Weight splitter -> paired layout [m][K/16][32]
// ---------------------------------------------------------------------------
__global__ __launch_bounds__(256)
void split_kernel(const float* __restrict__ in, float* __restrict__ out, int M, int K)
{
    const int i = blockIdx.x * 256 + threadIdx.x;
    if (i >= M * K) return;
    const int m = i / K;
    const int k = i - m * K;
    const float v = in[i];
    const float h = tf32r(v);
    float* dst = out + ((size_t)m * (K >> 4) + (k >> 4)) * 32 + pair16(k & 15);
    dst[0] = h;
    dst[1] = tf32r(v - h);
}

// ---------------------------------------------------------------------------
// GEMM1: 3-term split, paired A + paired B. K-chunk 16, TP=48, 2-stage,
// 2 CTAs/SM, block 128x128, 8 warps @ 32(M) x 64(N).
// Pairwise-nt MMA scheduling (dep distance 4) + pointer-increment addressing.
// ---------------------------------------------------------------------------
#define TP   48
#define STGF (256 * TP)
#define GEMM_SMEM (2 * STGF * 4)          // 98304 bytes

template<int NCH>
__global__ __launch_bounds__(256, 2)
void gemm_pair(const float* __restrict__ Ap, const float* __restrict__ Bp,
               float* __restrict__ C, int M)
{
    extern __shared__ float sm[];
    const int tid  = threadIdx.x;
    const int wid  = tid >> 5;
    const int lane = tid & 31;
    const int g    = lane >> 2;
    const int tig  = lane & 3;

    const int n0 = blockIdx.x * 128;
    const int m0 = blockIdx.y * 128;
    const int z  = blockIdx.z;

    const int wm = (wid & 3) * 32;
    const int wn = (wid >> 2) * 64;

    constexpr int K2 = NCH * 32;
    const float* Bb = Bp + (size_t)z * HW * (size_t)K2;
    float*       Cb = C  + (size_t)z * M * HW;

    uint32_t smb;
    asm("{ .reg .u64 t; cvta.to.shared.u64 t, %1; cvt.u32.u64 %0, t; }" : "=r"(smb) : "l"(sm));

    const int frow = tid >> 3;
    const int u8   = tid & 7;
    const float* gA = Ap + (size_t)(m0 + frow) * K2 + u8 * 4;
    const float* gB = Bb + (size_t)(n0 + frow) * K2 + u8 * 4;
    const uint32_t sA0 = smb + (uint32_t)(frow * TP + u8 * 4) * 4u;
    const uint32_t sB0 = sA0 + (uint32_t)(128 * TP) * 4u;
    const uint32_t sA1 = sA0 + STGF * 4u;
    const uint32_t sB1 = sB0 + STGF * 4u;

    float acc[2][8][4];
    #pragma unroll
    for (int mt = 0; mt < 2; mt++)
        #pragma unroll
        for (int nt = 0; nt < 8; nt++)
            #pragma unroll
            for (int j = 0; j < 4; j++) acc[mt][nt][j] = 0.f;

    // prologue: chunk 0 -> stage 0
    #pragma unroll
    for (int it = 0; it < 4; it++) {
        CP_ASYNC16(sA0 + (uint32_t)(it * 32 * TP) * 4u, gA + (size_t)it * 32 * K2);
        CP_ASYNC16(sB0 + (uint32_t)(it * 32 * TP) * 4u, gB + (size_t)it * 32 * K2);
    }
    CP_COMMIT();
    gA += 32;
    gB += 32;

    const float* stage0 = sm;
    const float* stage1 = sm + STGF;

    #pragma unroll 2
    for (int c = 0; c < NCH; c++) {
        CP_WAIT_ALL();
        __syncthreads();
        if (c + 1 < NCH) {
            const uint32_t dA = ((c + 1) & 1) ? sA1 : sA0;
            const uint32_t dB = ((c + 1) & 1) ? sB1 : sB0;
            #pragma unroll
            for (int it = 0; it < 4; it++) {
                CP_ASYNC16(dA + (uint32_t)(it * 32 * TP) * 4u, gA + (size_t)it * 32 * K2);
                CP_ASYNC16(dB + (uint32_t)(it * 32 * TP) * 4u, gB + (size_t)it * 32 * K2);
            }
            CP_COMMIT();
            gA += 32;
            gB += 32;
        }
        const float* As_ = (c & 1) ? stage1 : stage0;
        const float* Bs_ = As_ + 128 * TP;

        #pragma unroll
        for (int ks = 0; ks < 2; ks++) {
            const int col = ks * 16 + tig * 4;
            float4 r1 = *(const float4*)(As_ + (wm + g     ) * TP + col);
            float4 r2 = *(const float4*)(As_ + (wm + 8  + g) * TP + col);
            float4 r3 = *(const float4*)(As_ + (wm + 16 + g) * TP + col);
            float4 r4 = *(const float4*)(As_ + (wm + 24 + g) * TP + col);
            uint32_t ahi0[4] = { __float_as_uint(r1.x), __float_as_uint(r2.x),
                                 __float_as_uint(r1.z), __float_as_uint(r2.z) };
            uint32_t alo0[4] = { __float_as_uint(r1.y), __float_as_uint(r2.y),
                                 __float_as_uint(r1.w), __float_as_uint(r2.w) };
            uint32_t ahi1[4] = { __float_as_uint(r3.x), __float_as_uint(r4.x),
                                 __float_as_uint(r3.z), __float_as_uint(r4.z) };
            uint32_t alo1[4] = { __float_as_uint(r3.y), __float_as_uint(r4.y),
                                 __float_as_uint(r3.w), __float_as_uint(r4.w) };
            // pairwise nt: 12 MMAs, same-acc dependency distance = 4
            #pragma unroll
            for (int np = 0; np < 4; np++) {
                const int na = np * 2;
                const int nb = na + 1;
                float4 rb0 = *(const float4*)(Bs_ + (wn + na * 8 + g) * TP + col);
                float4 rb1 = *(const float4*)(Bs_ + (wn + nb * 8 + g) * TP + col);
                uint32_t b0h[2] = { __float_as_uint(rb0.x), __float_as_uint(rb0.z) };
                uint32_t b0l[2] = { __float_as_uint(rb0.y), __float_as_uint(rb0.w) };
                uint32_t b1h[2] = { __float_as_uint(rb1.x), __float_as_uint(rb1.z) };
                uint32_t b1l[2] = { __float_as_uint(rb1.y), __float_as_uint(rb1.w) };
                mma_tf32(acc[0][na], alo0, b0h);
                mma_tf32(acc[1][na], alo1, b0h);
                mma_tf32(acc[0][nb], alo0, b1h);
                mma_tf32(acc[1][nb], alo1, b1h);
                mma_tf32(acc[0][na], ahi0, b0l);
                mma_tf32(acc[1][na], ahi1, b0l);
                mma_tf32(acc[0][nb], ahi0, b1l);
                mma_tf32(acc[1][nb], ahi1, b1l);
                mma_tf32(acc[0][na], ahi0, b0h);
                mma_tf32(acc[1][na], ahi1, b0h);
                mma_tf32(acc[0][nb], ahi0, b1h);
                mma_tf32(acc[1][nb], ahi1, b1h);
            }
        }
    }

    #pragma unroll
    for (int mt = 0; mt < 2; mt++) {
        const int mA = m0 + wm + mt * 16 + g;
        const int mB = mA + 8;
        float* rowA = Cb + (size_t)mA * HW + n0 + wn + 2 * tig;
        float* rowB = Cb + (size_t)mB * HW + n0 + wn + 2 * tig;
        #pragma unroll
        for (int nt = 0; nt < 8; nt++) {
            *(float2*)(rowA + nt * 8) = make_float2(acc[mt][nt][0], acc[mt][nt][1]);
            *(float2*)(rowB + nt * 8) = make_float2(acc[mt][nt][2], acc[mt][nt][3]);
        }
    }
}

// ---------------------------------------------------------------------------
// GEMM2: 2-term split (AhBh + AlBh), paired A + HI-ONLY B.
// A tile 128xTP(48), B tile 128xTPB(24). NCH=32. Fused BN epilogue.
// Pairwise-nt scheduling + pointer-increment addressing.
// ---------------------------------------------------------------------------
#define TPB   24
#define STGF2 (128 * TP + 128 * TPB)
#define GEMM2_SMEM (2 * STGF2 * 4)         // 73728 bytes

__global__ __launch_bounds__(256, 2)
void gemm2_hi(const float* __restrict__ Ap, const float* __restrict__ Bp,
              float* __restrict__ C,
              const float* __restrict__ gamma, const float* __restrict__ beta,
              const float* __restrict__ mean,  const float* __restrict__ var)
{
    extern __shared__ float sm[];
    const int tid  = threadIdx.x;
    const int wid  = tid >> 5;
    const int lane = tid & 31;
    const int g    = lane >> 2;
    const int tig  = lane & 3;

    const int n0 = blockIdx.x * 128;
    const int m0 = blockIdx.y * 128;
    const int z  = blockIdx.z;

    const int wm = (wid & 3) * 32;
    const int wn = (wid >> 2) * 64;

    constexpr int NCH = 32;
    constexpr int K2A = NCH * 32;
    constexpr int K2B = NCH * 16;
    const float* Bb = Bp + (size_t)z * HW * (size_t)K2B;
    float*       Cb = C  + (size_t)z * OC_OUT * HW;

    uint32_t smb;
    asm("{ .reg .u64 t; cvta.to.shared.u64 t, %1; cvt.u32.u64 %0, t; }" : "=r"(smb) : "l"(sm));

    const int frowA = tid >> 3;
    const int u8    = tid & 7;
    const float* gA = Ap + (size_t)(m0 + frowA) * K2A + u8 * 4;
    const uint32_t sA0 = smb + (uint32_t)(frowA * TP + u8 * 4) * 4u;
    const int frowB = tid >> 2;
    const int u4    = tid & 3;
    const float* gB = Bb + (size_t)(n0 + frowB) * K2B + u4 * 4;
    const uint32_t sB0 = smb + (uint32_t)(128 * TP) * 4u
                             + (uint32_t)(frowB * TPB + u4 * 4) * 4u;
    const uint32_t sA1 = sA0 + STGF2 * 4u;
    const uint32_t sB1 = sB0 + STGF2 * 4u;

    float acc[2][8][4];
    #pragma unroll
    for (int mt = 0; mt < 2; mt++)
        #pragma unroll
        for (int nt = 0; nt < 8; nt++)
            #pragma unroll
            for (int j = 0; j < 4; j++) acc[mt][nt][j] = 0.f;

    #pragma unroll
    for (int it = 0; it < 4; it++)
        CP_ASYNC16(sA0 + (uint32_t)(it * 32 * TP) * 4u, gA + (size_t)it * 32 * K2A);
    #pragma unroll
    for (int it = 0; it < 2; it++)
        CP_ASYNC16(sB0 + (uint32_t)(it * 64 * TPB) * 4u, gB + (size_t)it * 64 * K2B);
    CP_COMMIT();
    gA += 32;
    gB += 16;

    const float* stage0 = sm;
    const float* stage1 = sm + STGF2;

    #pragma unroll 2
    for (int c = 0; c < NCH; c++) {
        CP_WAIT_ALL();
        __syncthreads();
        if (c + 1 < NCH) {
            const uint32_t dA = ((c + 1) & 1) ? sA1 : sA0;
            const uint32_t dB = ((c + 1) & 1) ? sB1 : sB0;
            #pragma unroll
            for (int it = 0; it < 4; it++)
                CP_ASYNC16(dA + (uint32_t)(it * 32 * TP) * 4u, gA + (size_t)it * 32 * K2A);
            #pragma unroll
            for (int it = 0; it < 2; it++)
                CP_ASYNC16(dB + (uint32_t)(it * 64 * TPB) * 4u, gB + (size_t)it * 64 * K2B);
            CP_COMMIT();
            gA += 32;
            gB += 16;
        }
        const float* As_ = (c & 1) ? stage1 : stage0;
        const float* Bs_ = As_ + 128 * TP;

        #pragma unroll
        for (int ks = 0; ks < 2; ks++) {
            const int colA = ks * 16 + tig * 4;
            const int colB = ks * 8 + tig * 2;
            float4 r1 = *(const float4*)(As_ + (wm + g     ) * TP + colA);
            float4 r2 = *(const float4*)(As_ + (wm + 8  + g) * TP + colA);
            float4 r3 = *(const float4*)(As_ + (wm + 16 + g) * TP + colA);
            float4 r4 = *(const float4*)(As_ + (wm + 24 + g) * TP + colA);
            uint32_t ahi0[4] = { __float_as_uint(r1.x), __float_as_uint(r2.x),
                                 __float_as_uint(r1.z), __float_as_uint(r2.z) };
            uint32_t alo0[4] = { __float_as_uint(r1.y), __float_as_uint(r2.y),
                                 __float_as_uint(r1.w), __float_as_uint(r2.w) };
            uint32_t ahi1[4] = { __float_as_uint(r3.x), __float_as_uint(r4.x),
                                 __float_as_uint(r3.z), __float_as_uint(r4.z) };
            uint32_t alo1[4] = { __float_as_uint(r3.y), __float_as_uint(r4.y),
                                 __float_as_uint(r3.w), __float_as_uint(r4.w) };
            // pairwise nt: 8 MMAs, same-acc dependency distance = 4
            #pragma unroll
            for (int np = 0; np < 4; np++) {
                const int na = np * 2;
                const int nb = na + 1;
                float2 rb0 = *(const float2*)(Bs_ + (wn + na * 8 + g) * TPB + colB);
                float2 rb1 = *(const float2*)(Bs_ + (wn + nb * 8 + g) * TPB + colB);
                uint32_t b0[2] = { __float_as_uint(rb0.x), __float_as_uint(rb0.y) };
                uint32_t b1[2] = { __float_as_uint(rb1.x), __float_as_uint(rb1.y) };
                mma_tf32(acc[0][na], alo0, b0);
                mma_tf32(acc[1][na], alo1, b0);
                mma_tf32(acc[0][nb], alo0, b1);
                mma_tf32(acc[1][nb], alo1, b1);
                mma_tf32(acc[0][na], ahi0, b0);
                mma_tf32(acc[1][na], ahi1, b0);
                mma_tf32(acc[0][nb], ahi0, b1);
                mma_tf32(acc[1][nb], ahi1, b1);
            }
        }
    }

    #pragma unroll
    for (int mt = 0; mt < 2; mt++) {
        const int mA = m0 + wm + mt * 16 + g;
        const int mB = mA + 8;
        const float invA = gamma[mA] * rsqrtf(var[mA] + 1e-5f);
        const float invB = gamma[mB] * rsqrtf(var[mB] + 1e-5f);
        const float hA = beta[mA] - mean[mA] * invA;
        const float hB = beta[mB] - mean[mB] * invB;
        float* rowA = Cb + (size_t)mA * HW + n0 + wn + 2 * tig;
        float* rowB = Cb + (size_t)mB * HW + n0 + wn + 2 * tig;
        #pragma unroll
        for (int nt = 0; nt < 8; nt++) {
            *(float2*)(rowA + nt * 8) =
                make_float2(acc[mt][nt][0] * invA + hA, acc[mt][nt][1] * invA + hA);
            *(float2*)(rowB + nt * 8) =
                make_float2(acc[mt][nt][2] * invB + hB, acc[mt][nt][3] * invB + hB);
        }
    }
}

// ---------------------------------------------------------------------------
// Transpose x: [b][k=256][n] -> paired xt [b][n][16][32]
// ---------------------------------------------------------------------------
__global__ __launch_bounds__(256)
void transpose_kernel(const float* __restrict__ in, float* __restrict__ outp)
{
    __shared__ float t[32][33];
    const int b  = blockIdx.z;
    const int n0 = blockIdx.x * 32;
    const int k0 = blockIdx.y * 32;
    const int tx = threadIdx.x & 31;
    const int ty = threadIdx.x >> 5;

    const float* ib = in + (size_t)b * CIN * HW;
    float* ob = outp + (size_t)b * HW * (2 * CIN);

    #pragma unroll
    for (int i = 0; i < 4; i++) {
        const int k = k0 + ty + i * 8;
        t[ty + i * 8][tx] = ib[(size_t)k * HW + n0 + tx];
    }
    __syncthreads();
    #pragma unroll
    for (int i = 0; i < 4; i++) {
        const int n = n0 + ty + i * 8;
        const int k = k0 + tx;
        const float v = t[tx][ty + i * 8];
        const float h = tf32r(v);
        float* dst = ob + (size_t)n * (2 * CIN) + (k >> 4) * 32 + pair16(k & 15);
        dst[0] = h;
        dst[1] = tf32r(v - h);
    }
}

// ---------------------------------------------------------------------------
// Fused depthwise 3x3 + grouped 1x1
// ---------------------------------------------------------------------------
__global__ __launch_bounds__(256)
void dwpw_kernel(const float* __restrict__ qkv,
                 const float* __restrict__ wdw,
                 const float* __restrict__ wpw,
                 float* __restrict__ agg)
{
    const int strip = blockIdx.x;
    const int gg    = blockIdx.y;
    const int b     = blockIdx.z;
    const int r0    = strip * 16;

    __shared__ float s_in[8][18][68];
    __shared__ float s_wdw[8][9];
    __shared__ float s_wpw[8][8];

    const int tid = threadIdx.x;
    const float* base = qkv + ((size_t)b * OC_QKV + gg * 8) * HW;

    for (int idx = tid; idx < 8 * 18 * 16; idx += 256) {
        const int seg = idx & 15;
        const int row = idx >> 4;
        const int rr  = row % 18;
        const int ch  = row / 18;
        const int y   = r0 + rr - 1;
        float4 v = make_float4(0.f, 0.f, 0.f, 0.f);
        if (y >= 0 && y < HH)
            v = *(const float4*)(base + (size_t)ch * HW + y * WW + seg * 4);
        float* d = &s_in[ch][rr][1 + seg * 4];
        d[0] = v.x; d[1] = v.y; d[2] = v.z; d[3] = v.w;
        if (seg == 0)  s_in[ch][rr][0]  = 0.f;
        if (seg == 15) s_in[ch][rr][65] = 0.f;
    }
    if (tid < 72)
        s_wdw[tid / 9][tid % 9] = wdw[(size_t)(gg * 8 + tid / 9) * 9 + tid % 9];
    if (tid >= 128 && tid < 192) {
        int t = tid - 128;
        s_wpw[t >> 3][t & 7] = wpw[(size_t)(gg * 8 + (t >> 3)) * 8 + (t & 7)];
    }
    __syncthreads();

    float* obase = agg + ((size_t)b * OC_QKV + gg * 8) * HW + r0 * WW;
    for (int p = tid; p < 16 * WW; p += 256) {
        const int py = p >> 6;
        const int px = p & 63;
        float dwv[8];
        #pragma unroll
        for (int ic = 0; ic < 8; ic++) {
            float s = 0.f;
            #pragma unroll
            for (int ky = 0; ky < 3; ky++)
                #pragma unroll
                for (int kx = 0; kx < 3; kx++)
                    s += s_in[ic][py + ky][px + kx] * s_wdw[ic][ky * 3 + kx];
            dwv[ic] = s;
        }
        #pragma unroll
        for (int oc = 0; oc < 8; oc++) {
            float s = 0.f;
            #pragma unroll
            for (int ic = 0; ic < 8; ic++) s += s_wpw[oc][ic] * dwv[ic];
            obase[(size_t)oc * HW + p] = s;
        }
    }
}

// ---------------------------------------------------------------------------
// kv partial reduction over 4 n-segments
// ---------------------------------------------------------------------------
__global__ __launch_bounds__(256)
void kv_kernel(const float* __restrict__ qkv, const float* __restrict__ agg,
               float* __restrict__ kvout)
{
    const int h   = blockIdx.x;
    const int b   = blockIdx.y;
    const int seg = blockIdx.z;
    const float* src = (h < 32) ? qkv : agg;
    const int ch0 = (h & 31) * 24;
    const float* base = src + ((size_t)b * OC_QKV + ch0) * HW;

    float acc[8][9];
    #pragma unroll
    for (int d = 0; d < 8; d++)
        #pragma unroll
        for (int e = 0; e < 9; e++) acc[d][e] = 0.f;

    const int nend = (seg + 1) * 1024;
    for (int n = seg * 1024 + threadIdx.x; n < nend; n += 256) {
        float kk[8], vv[8];
        #pragma unroll
        for (int d = 0; d < 8; d++)
            kk[d] = fmaxf(base[(size_t)(8 + d) * HW + n], 0.f);
        #pragma unroll
        for (int e = 0; e < 8; e++)
            vv[e] = base[(size_t)(16 + e) * HW + n];
        #pragma unroll
        for (int d = 0; d < 8; d++) {
            #pragma unroll
            for (int e = 0; e < 8; e++) acc[d][e] += kk[d] * vv[e];
            acc[d][8] += kk[d];
        }
    }

    __shared__ float sred[8][72];
    const int lane = threadIdx.x & 31;
    const int warp = threadIdx.x >> 5;
    #pragma unroll
    for (int d = 0; d < 8; d++)
        #pragma unroll
        for (int e = 0; e < 9; e++) {
            float v = acc[d][e];
            #pragma unroll
            for (int o = 16; o > 0; o >>= 1)
                v += __shfl_down_sync(0xffffffffu, v, o);
            if (lane == 0) sred[warp][d * 9 + e] = v;
        }
    __syncthreads();
    if (threadIdx.x < 72) {
        float s = 0.f;
        #pragma unroll
        for (int w = 0; w < 8; w++) s += sred[w][threadIdx.x];
        kvout[(((size_t)b * HEADS + h) * 4 + seg) * 72 + threadIdx.x] = s;
    }
}

// ---------------------------------------------------------------------------
// attention apply -> hi-only att [b][n][512] in frag order
// ---------------------------------------------------------------------------
__global__ __launch_bounds__(256)
void apply_kernel(const float* __restrict__ qkv, const float* __restrict__ agg,
                  const float* __restrict__ kvin, float* __restrict__ attp)
{
    const int h = blockIdx.x;
    const int b = blockIdx.y;
    const float* src = (h < 32) ? qkv : agg;
    const int ch0 = (h & 31) * 24;
    const float* qb = src + ((size_t)b * OC_QKV + ch0) * HW;

    __shared__ float s_kv[72];
    if (threadIdx.x < 72) {
        const float* kp = kvin + ((size_t)b * HEADS + h) * 4 * 72 + threadIdx.x;
        s_kv[threadIdx.x] = kp[0] + kp[72] + kp[144] + kp[216];
    }
    __syncthreads();

    float* ob = attp + (size_t)b * HW * ATT_CH + (h >> 1) * 16 + (h & 1) * 8;
    for (int n = threadIdx.x; n < HW; n += 256) {
        float q[8];
        #pragma unroll
        for (int d = 0; d < 8; d++)
            q[d] = fmaxf(qb[(size_t)d * HW + n], 0.f);
        float num[9];
        #pragma unroll
        for (int e = 0; e < 9; e++) {
            float s = 0.f;
            #pragma unroll
            for (int d = 0; d < 8; d++) s += q[d] * s_kv[d * 9 + e];
            num[e] = s;
        }
        const float r = 1.0f / (num[8] + 1e-15f);
        float hv[8];
        #pragma unroll
        for (int d = 0; d < 8; d++)
            hv[d] = tf32r(num[d] * r);
        float* dst = ob + (size_t)n * ATT_CH;
        *(float4*)(dst + 0) = make_float4(hv[0], hv[4], hv[1], hv[5]);
        *(float4*)(dst + 4) = make_float4(hv[2], hv[6], hv[3], hv[7]);
    }
}

// ---------------------------------------------------------------------------
// Launch
// ---------------------------------------------------------------------------
extern "C" void kernel_launch(void* const* d_in, const int* in_sizes, int n_in,
                              void* d_out, int out_size)
{
    const float* x      = (const float*)d_in[0];
    const float* w_qkv  = (const float*)d_in[1];
    const float* w_dw   = (const float*)d_in[2];
    const float* w_pw   = (const float*)d_in[3];
    const float* w_proj = (const float*)d_in[4];
    const float* gamma  = (const float*)d_in[5];
    const float* beta   = (const float*)d_in[6];
    const float* mean   = (const float*)d_in[7];
    const float* var    = (const float*)d_in[8];
    float* out = (float*)d_out;

    float *qkv_p, *agg_p, *kv_p, *attp_p, *xtp_p, *wqp_p, *wpp_p;
    cudaGetSymbolAddress((void**)&qkv_p,  g_qkv);
    cudaGetSymbolAddress((void**)&agg_p,  g_agg);
    cudaGetSymbolAddress((void**)&kv_p,   g_kv);
    cudaGetSymbolAddress((void**)&attp_p, g_attp);
    cudaGetSymbolAddress((void**)&xtp_p,  g_xtp);
    cudaGetSymbolAddress((void**)&wqp_p,  g_wqp);
    cudaGetSymbolAddress((void**)&wpp_p,  g_wpp);

    cudaFuncSetAttribute(gemm_pair<16>, cudaFuncAttributeMaxDynamicSharedMemorySize, GEMM_SMEM);
    cudaFuncSetAttribute(gemm2_hi, cudaFuncAttributeMaxDynamicSharedMemorySize, GEMM2_SMEM);

    split_kernel<<<(OC_QKV * CIN + 255) / 256, 256>>>(w_qkv, wqp_p, OC_QKV, CIN);
    split_kernel<<<(OC_OUT * K_PROJ + 255) / 256, 256>>>(w_proj, wpp_p, OC_OUT, K_PROJ);
    {
        dim3 grid(HW / 32, CIN / 32, BATCH);
        transpose_kernel<<<grid, 256>>>(x, xtp_p);
    }
    // 1) qkv = W_qkv * x : 3-term
    {
        dim3 grid(HW / 128, OC_QKV / 128, BATCH);
        gemm_pair<16><<<grid, 256, GEMM_SMEM>>>(wqp_p, xtp_p, qkv_p, OC_QKV);
    }
    // 2) depthwise + grouped pointwise
    {
        dim3 grid(4, 96, BATCH);
        dwpw_kernel<<<grid, 256>>>(qkv_p, w_dw, w_pw, agg_p);
    }
    // 3) kv partial reduction
    {
        dim3 grid(HEADS, BATCH, 4);
        kv_kernel<<<grid, 256>>>(qkv_p, agg_p, kv_p);
    }
    // 4) attention apply (hi-only att)
    {
        dim3 grid(HEADS, BATCH);
        apply_kernel<<<grid, 256>>>(qkv_p, agg_p, kv_p, attp_p);
    }
    // 5) y = W_proj * att + BN : 2-term, hi-only B
    {
        dim3 grid(HW / 128, OC_OUT / 128, BATCH);
        gemm2_hi<<<grid, 256, GEMM2_SMEM>>>(wpp_p, attp_p, out,
                                            gamma, beta, mean, var);
    }
}

// round 12
// speedup vs baseline: 1.2573x; 1.2573x over previous
#include <cuda_runtime.h>
#include <cuda_fp16.h>
#include <cstdint>
#include <cstddef>

// Problem constants
#define BATCH   16
#define CIN     256
#define HH      64
#define WW      64
#define HW      4096
#define OC_QKV  768
#define HEADS   64
#define ATT_CH  512
#define OC_OUT  256
#define K_PROJ  512

#define WSCALE    2048.0f
#define INV_WSCALE (1.0f / 2048.0f)

// ---------------------------------------------------------------------------
// fp16 hi/lo paired layout, 16-k chunks, 32 halves (64B) per row per chunk.
// slot s(p) = ((p&3)<<1)|(p>>2) for pair p=kk>>1; slot = 8B = [h_e,h_o,l_e,l_o].
// A thread's m16n8k16 fragment (hi+lo) = one LDS.128 at byte offset tig*16.
// ---------------------------------------------------------------------------
__device__ float  g_qkv [(size_t)BATCH * OC_QKV * HW];
__device__ float  g_agg [(size_t)BATCH * OC_QKV * HW];
__device__ float  g_kv  [(size_t)BATCH * HEADS * 4 * 72];
__device__ __half g_attp[(size_t)BATCH * HW * 2 * ATT_CH];  // paired fp16
__device__ __half g_xtp [(size_t)BATCH * HW * 2 * CIN];     // paired fp16
__device__ __half g_wqp [(size_t)OC_QKV * 2 * CIN];
__device__ __half g_wpp [(size_t)OC_OUT * 2 * K_PROJ];

// ---------------------------------------------------------------------------
// Helpers
// ---------------------------------------------------------------------------
__device__ __forceinline__ int slot_hi(int kk) {   // half-offset of hi in 32-half chunk
    const int p = kk >> 1;
    const int s = ((p & 3) << 1) | (p >> 2);
    return s * 4 + (kk & 1);
}
__device__ __forceinline__ void mma_f16(float* d, const uint32_t* a, const uint32_t* b) {
    asm volatile(
        "mma.sync.aligned.m16n8k16.row.col.f32.f16.f16.f32 "
        "{%0,%1,%2,%3}, {%4,%5,%6,%7}, {%8,%9}, {%0,%1,%2,%3};"
        : "+f"(d[0]), "+f"(d[1]), "+f"(d[2]), "+f"(d[3])
        : "r"(a[0]), "r"(a[1]), "r"(a[2]), "r"(a[3]), "r"(b[0]), "r"(b[1]));
}
#define CP_ASYNC16(sa, gp) \
    asm volatile("cp.async.ca.shared.global [%0], [%1], 16;" :: "r"(sa), "l"(gp))
#define CP_COMMIT() asm volatile("cp.async.commit_group;")
#define CP_WAIT_ALL() asm volatile("cp.async.wait_group 0;")

// ---------------------------------------------------------------------------
// Splitter: fp32 [M,K] row-major -> fp16 hi/lo paired [m][K/16][32 halves]
// ---------------------------------------------------------------------------
__global__ __launch_bounds__(256)
void split_kernel(const float* __restrict__ in, __half* __restrict__ out,
                  int M, int K, float scale)
{
    const int i = blockIdx.x * 256 + threadIdx.x;
    if (i >= M * K) return;
    const int m = i / K;
    const int k = i - m * K;
    const float v = in[i] * scale;
    const __half h = __float2half_rn(v);
    const __half l = __float2half_rn(v - __half2float(h));
    __half* dst = out + ((size_t)m * (K >> 4) + (k >> 4)) * 32;
    const int off = slot_hi(k & 15);
    dst[off]     = h;
    dst[off + 2] = l;
}

// ---------------------------------------------------------------------------
// Unified fp16 3-term GEMM:  C[z] = A * B[z]^T  (per-batch B)
//   A: [M, K] paired fp16 (scaled by WSCALE), B: [HW, K] paired fp16
//   3 MMAs per k16 step: AlBh, AhBl, AhBh (fp32 accum).
// Block 128x128, K-chunk 16 (one k16 step), 2-stage cp.async, 2 CTAs/SM.
// 8 warps @ 32(M) x 64(N). Stage = 16KB (A 8KB + B 8KB).
// ---------------------------------------------------------------------------
#define STGB 16384
#define GEMM_SMEM (2 * STGB)

template<int NCH, bool BN>
__global__ __launch_bounds__(256, 2)
void gemm_fp16(const __half* __restrict__ Ap, const __half* __restrict__ Bp,
               float* __restrict__ C, int M,
               const float* __restrict__ gamma, const float* __restrict__ beta,
               const float* __restrict__ mean,  const float* __restrict__ var)
{
    extern __shared__ char sm[];
    const int tid  = threadIdx.x;
    const int wid  = tid >> 5;
    const int lane = tid & 31;
    const int g    = lane >> 2;
    const int tig  = lane & 3;

    const int n0 = blockIdx.x * 128;
    const int m0 = blockIdx.y * 128;
    const int z  = blockIdx.z;

    const int wm = (wid & 3) * 32;
    const int wn = (wid >> 2) * 64;

    constexpr int ROWB = NCH * 64;          // bytes per gmem row
    const char* Ab = (const char*)Ap;
    const char* Bb = (const char*)Bp + (size_t)z * HW * ROWB;
    float*      Cb = C + (size_t)z * M * HW;

    uint32_t smb;
    asm("{ .reg .u64 t; cvta.to.shared.u64 t, %1; cvt.u32.u64 %0, t; }" : "=r"(smb) : "l"(sm));

    // fill mapping: frow = tid>>2 (0..63, +64 second pass), u4 = tid&3 (16B block)
    const int frow = tid >> 2;
    const int u4   = tid & 3;
    const char* gA = Ab + (size_t)(m0 + frow) * ROWB + u4 * 16;
    const char* gB = Bb + (size_t)(n0 + frow) * ROWB + u4 * 16;
    const uint32_t sA0 = smb + (uint32_t)(frow * 64 + u4 * 16);
    const uint32_t sB0 = sA0 + 8192u;

    float acc[2][8][4];
    #pragma unroll
    for (int mt = 0; mt < 2; mt++)
        #pragma unroll
        for (int nt = 0; nt < 8; nt++)
            #pragma unroll
            for (int j = 0; j < 4; j++) acc[mt][nt][j] = 0.f;

    // prologue: chunk 0 -> stage 0
    CP_ASYNC16(sA0,         gA);
    CP_ASYNC16(sA0 + 4096u, gA + (size_t)64 * ROWB);
    CP_ASYNC16(sB0,         gB);
    CP_ASYNC16(sB0 + 4096u, gB + (size_t)64 * ROWB);
    CP_COMMIT();
    gA += 64;
    gB += 64;

    for (int c = 0; c < NCH; c++) {
        CP_WAIT_ALL();
        __syncthreads();
        if (c + 1 < NCH) {
            const uint32_t so = ((c + 1) & 1) ? STGB : 0u;
            CP_ASYNC16(sA0 + so,         gA);
            CP_ASYNC16(sA0 + so + 4096u, gA + (size_t)64 * ROWB);
            CP_ASYNC16(sB0 + so,         gB);
            CP_ASYNC16(sB0 + so + 4096u, gB + (size_t)64 * ROWB);
            CP_COMMIT();
            gA += 64;
            gB += 64;
        }
        const char* As_ = sm + (c & 1) * STGB;
        const char* Bs_ = As_ + 8192;

        const int col = tig * 16;
        float4 r1 = *(const float4*)(As_ + (wm + g     ) * 64 + col);
        float4 r2 = *(const float4*)(As_ + (wm + 8  + g) * 64 + col);
        float4 r3 = *(const float4*)(As_ + (wm + 16 + g) * 64 + col);
        float4 r4 = *(const float4*)(As_ + (wm + 24 + g) * 64 + col);
        uint32_t ahi0[4] = { __float_as_uint(r1.x), __float_as_uint(r2.x),
                             __float_as_uint(r1.z), __float_as_uint(r2.z) };
        uint32_t alo0[4] = { __float_as_uint(r1.y), __float_as_uint(r2.y),
                             __float_as_uint(r1.w), __float_as_uint(r2.w) };
        uint32_t ahi1[4] = { __float_as_uint(r3.x), __float_as_uint(r4.x),
                             __float_as_uint(r3.z), __float_as_uint(r4.z) };
        uint32_t alo1[4] = { __float_as_uint(r3.y), __float_as_uint(r4.y),
                             __float_as_uint(r3.w), __float_as_uint(r4.w) };

        #pragma unroll
        for (int np = 0; np < 4; np++) {
            const int na = np * 2;
            const int nb = na + 1;
            float4 rb0 = *(const float4*)(Bs_ + (wn + na * 8 + g) * 64 + col);
            float4 rb1 = *(const float4*)(Bs_ + (wn + nb * 8 + g) * 64 + col);
            uint32_t b0h[2] = { __float_as_uint(rb0.x), __float_as_uint(rb0.z) };
            uint32_t b0l[2] = { __float_as_uint(rb0.y), __float_as_uint(rb0.w) };
            uint32_t b1h[2] = { __float_as_uint(rb1.x), __float_as_uint(rb1.z) };
            uint32_t b1l[2] = { __float_as_uint(rb1.y), __float_as_uint(rb1.w) };
            mma_f16(acc[0][na], alo0, b0h);
            mma_f16(acc[1][na], alo1, b0h);
            mma_f16(acc[0][nb], alo0, b1h);
            mma_f16(acc[1][nb], alo1, b1h);
            mma_f16(acc[0][na], ahi0, b0l);
            mma_f16(acc[1][na], ahi1, b0l);
            mma_f16(acc[0][nb], ahi0, b1l);
            mma_f16(acc[1][nb], ahi1, b1l);
            mma_f16(acc[0][na], ahi0, b0h);
            mma_f16(acc[1][na], ahi1, b0h);
            mma_f16(acc[0][nb], ahi0, b1h);
            mma_f16(acc[1][nb], ahi1, b1h);
        }
    }

    // epilogue (undo WSCALE; optional fused BN)
    #pragma unroll
    for (int mt = 0; mt < 2; mt++) {
        const int mA = m0 + wm + mt * 16 + g;
        const int mB = mA + 8;
        float sAa = INV_WSCALE, hA = 0.f, sBb = INV_WSCALE, hB = 0.f;
        if (BN) {
            const float invA = gamma[mA] * rsqrtf(var[mA] + 1e-5f);
            const float invB = gamma[mB] * rsqrtf(var[mB] + 1e-5f);
            sAa = invA * INV_WSCALE;
            hA  = beta[mA] - mean[mA] * invA;
            sBb = invB * INV_WSCALE;
            hB  = beta[mB] - mean[mB] * invB;
        }
        float* rowA = Cb + (size_t)mA * HW + n0 + wn + 2 * tig;
        float* rowB = Cb + (size_t)mB * HW + n0 + wn + 2 * tig;
        #pragma unroll
        for (int nt = 0; nt < 8; nt++) {
            *(float2*)(rowA + nt * 8) =
                make_float2(acc[mt][nt][0] * sAa + hA, acc[mt][nt][1] * sAa + hA);
            *(float2*)(rowB + nt * 8) =
                make_float2(acc[mt][nt][2] * sBb + hB, acc[mt][nt][3] * sBb + hB);
        }
    }
}

// ---------------------------------------------------------------------------
// Transpose x: [b][k=256][n] -> paired fp16 xt [b][n][16 chunks][32 halves]
// ---------------------------------------------------------------------------
__global__ __launch_bounds__(256)
void transpose_kernel(const float* __restrict__ in, __half* __restrict__ outp)
{
    __shared__ float t[32][33];
    const int b  = blockIdx.z;
    const int n0 = blockIdx.x * 32;
    const int k0 = blockIdx.y * 32;
    const int tx = threadIdx.x & 31;
    const int ty = threadIdx.x >> 5;

    const float* ib = in + (size_t)b * CIN * HW;
    __half* ob = outp + (size_t)b * HW * (2 * CIN);

    #pragma unroll
    for (int i = 0; i < 4; i++) {
        const int k = k0 + ty + i * 8;
        t[ty + i * 8][tx] = ib[(size_t)k * HW + n0 + tx];
    }
    __syncthreads();
    #pragma unroll
    for (int i = 0; i < 4; i++) {
        const int n = n0 + ty + i * 8;
        const int k = k0 + tx;
        const float v = t[tx][ty + i * 8];
        const __half h = __float2half_rn(v);
        const __half l = __float2half_rn(v - __half2float(h));
        __half* dst = ob + (size_t)n * (2 * CIN) + (k >> 4) * 32;
        const int off = slot_hi(k & 15);
        dst[off]     = h;
        dst[off + 2] = l;
    }
}

// ---------------------------------------------------------------------------
// Fused depthwise 3x3 + grouped 1x1 (fp32, unchanged)
// ---------------------------------------------------------------------------
__global__ __launch_bounds__(256)
void dwpw_kernel(const float* __restrict__ qkv,
                 const float* __restrict__ wdw,
                 const float* __restrict__ wpw,
                 float* __restrict__ agg)
{
    const int strip = blockIdx.x;
    const int gg    = blockIdx.y;
    const int b     = blockIdx.z;
    const int r0    = strip * 16;

    __shared__ float s_in[8][18][68];
    __shared__ float s_wdw[8][9];
    __shared__ float s_wpw[8][8];

    const int tid = threadIdx.x;
    const float* base = qkv + ((size_t)b * OC_QKV + gg * 8) * HW;

    for (int idx = tid; idx < 8 * 18 * 16; idx += 256) {
        const int seg = idx & 15;
        const int row = idx >> 4;
        const int rr  = row % 18;
        const int ch  = row / 18;
        const int y   = r0 + rr - 1;
        float4 v = make_float4(0.f, 0.f, 0.f, 0.f);
        if (y >= 0 && y < HH)
            v = *(const float4*)(base + (size_t)ch * HW + y * WW + seg * 4);
        float* d = &s_in[ch][rr][1 + seg * 4];
        d[0] = v.x; d[1] = v.y; d[2] = v.z; d[3] = v.w;
        if (seg == 0)  s_in[ch][rr][0]  = 0.f;
        if (seg == 15) s_in[ch][rr][65] = 0.f;
    }
    if (tid < 72)
        s_wdw[tid / 9][tid % 9] = wdw[(size_t)(gg * 8 + tid / 9) * 9 + tid % 9];
    if (tid >= 128 && tid < 192) {
        int t = tid - 128;
        s_wpw[t >> 3][t & 7] = wpw[(size_t)(gg * 8 + (t >> 3)) * 8 + (t & 7)];
    }
    __syncthreads();

    float* obase = agg + ((size_t)b * OC_QKV + gg * 8) * HW + r0 * WW;
    for (int p = tid; p < 16 * WW; p += 256) {
        const int py = p >> 6;
        const int px = p & 63;
        float dwv[8];
        #pragma unroll
        for (int ic = 0; ic < 8; ic++) {
            float s = 0.f;
            #pragma unroll
            for (int ky = 0; ky < 3; ky++)
                #pragma unroll
                for (int kx = 0; kx < 3; kx++)
                    s += s_in[ic][py + ky][px + kx] * s_wdw[ic][ky * 3 + kx];
            dwv[ic] = s;
        }
        #pragma unroll
        for (int oc = 0; oc < 8; oc++) {
            float s = 0.f;
            #pragma unroll
            for (int ic = 0; ic < 8; ic++) s += s_wpw[oc][ic] * dwv[ic];
            obase[(size_t)oc * HW + p] = s;
        }
    }
}

// ---------------------------------------------------------------------------
// kv partial reduction over 4 n-segments (unchanged)
// ---------------------------------------------------------------------------
__global__ __launch_bounds__(256)
void kv_kernel(const float* __restrict__ qkv, const float* __restrict__ agg,
               float* __restrict__ kvout)
{
    const int h   = blockIdx.x;
    const int b   = blockIdx.y;
    const int seg = blockIdx.z;
    const float* src = (h < 32) ? qkv : agg;
    const int ch0 = (h & 31) * 24;
    const float* base = src + ((size_t)b * OC_QKV + ch0) * HW;

    float acc[8][9];
    #pragma unroll
    for (int d = 0; d < 8; d++)
        #pragma unroll
        for (int e = 0; e < 9; e++) acc[d][e] = 0.f;

    const int nend = (seg + 1) * 1024;
    for (int n = seg * 1024 + threadIdx.x; n < nend; n += 256) {
        float kk[8], vv[8];
        #pragma unroll
        for (int d = 0; d < 8; d++)
            kk[d] = fmaxf(base[(size_t)(8 + d) * HW + n], 0.f);
        #pragma unroll
        for (int e = 0; e < 8; e++)
            vv[e] = base[(size_t)(16 + e) * HW + n];
        #pragma unroll
        for (int d = 0; d < 8; d++) {
            #pragma unroll
            for (int e = 0; e < 8; e++) acc[d][e] += kk[d] * vv[e];
            acc[d][8] += kk[d];
        }
    }

    __shared__ float sred[8][72];
    const int lane = threadIdx.x & 31;
    const int warp = threadIdx.x >> 5;
    #pragma unroll
    for (int d = 0; d < 8; d++)
        #pragma unroll
        for (int e = 0; e < 9; e++) {
            float v = acc[d][e];
            #pragma unroll
            for (int o = 16; o > 0; o >>= 1)
                v += __shfl_down_sync(0xffffffffu, v, o);
            if (lane == 0) sred[warp][d * 9 + e] = v;
        }
    __syncthreads();
    if (threadIdx.x < 72) {
        float s = 0.f;
        #pragma unroll
        for (int w = 0; w < 8; w++) s += sred[w][threadIdx.x];
        kvout[(((size_t)b * HEADS + h) * 4 + seg) * 72 + threadIdx.x] = s;
    }
}

// ---------------------------------------------------------------------------
// attention apply -> paired fp16 att. Head h: chunk h>>1, slots (j<<1)|(h&1),
// each slot 8B = [h(v2j), h(v2j+1), l(v2j), l(v2j+1)].
// ---------------------------------------------------------------------------
__global__ __launch_bounds__(256)
void apply_kernel(const float* __restrict__ qkv, const float* __restrict__ agg,
                  const float* __restrict__ kvin, __half* __restrict__ attp)
{
    const int h = blockIdx.x;
    const int b = blockIdx.y;
    const float* src = (h < 32) ? qkv : agg;
    const int ch0 = (h & 31) * 24;
    const float* qb = src + ((size_t)b * OC_QKV + ch0) * HW;

    __shared__ float s_kv[72];
    if (threadIdx.x < 72) {
        const float* kp = kvin + ((size_t)b * HEADS + h) * 4 * 72 + threadIdx.x;
        s_kv[threadIdx.x] = kp[0] + kp[72] + kp[144] + kp[216];
    }
    __syncthreads();

    char* ob = (char*)attp + (size_t)b * HW * 2048 + (h >> 1) * 64;
    const int hodd = h & 1;
    for (int n = threadIdx.x; n < HW; n += 256) {
        float q[8];
        #pragma unroll
        for (int d = 0; d < 8; d++)
            q[d] = fmaxf(qb[(size_t)d * HW + n], 0.f);
        float num[9];
        #pragma unroll
        for (int e = 0; e < 9; e++) {
            float s = 0.f;
            #pragma unroll
            for (int d = 0; d < 8; d++) s += q[d] * s_kv[d * 9 + e];
            num[e] = s;
        }
        const float r = 1.0f / (num[8] + 1e-15f);
        char* p = ob + (size_t)n * 2048;
        #pragma unroll
        for (int j = 0; j < 4; j++) {
            const float v0 = num[2 * j] * r;
            const float v1 = num[2 * j + 1] * r;
            const __half h0 = __float2half_rn(v0);
            const __half h1 = __float2half_rn(v1);
            const __half l0 = __float2half_rn(v0 - __half2float(h0));
            const __half l1 = __float2half_rn(v1 - __half2float(h1));
            __half2 ph = __halves2half2(h0, h1);
            __half2 pl = __halves2half2(l0, l1);
            uint2 w;
            w.x = *reinterpret_cast<unsigned*>(&ph);
            w.y = *reinterpret_cast<unsigned*>(&pl);
            *(uint2*)(p + ((j << 1) | hodd) * 8) = w;
        }
    }
}

// ---------------------------------------------------------------------------
// Launch
// ---------------------------------------------------------------------------
extern "C" void kernel_launch(void* const* d_in, const int* in_sizes, int n_in,
                              void* d_out, int out_size)
{
    const float* x      = (const float*)d_in[0];
    const float* w_qkv  = (const float*)d_in[1];
    const float* w_dw   = (const float*)d_in[2];
    const float* w_pw   = (const float*)d_in[3];
    const float* w_proj = (const float*)d_in[4];
    const float* gamma  = (const float*)d_in[5];
    const float* beta   = (const float*)d_in[6];
    const float* mean   = (const float*)d_in[7];
    const float* var    = (const float*)d_in[8];
    float* out = (float*)d_out;

    float *qkv_p, *agg_p, *kv_p;
    __half *attp_p, *xtp_p, *wqp_p, *wpp_p;
    cudaGetSymbolAddress((void**)&qkv_p,  g_qkv);
    cudaGetSymbolAddress((void**)&agg_p,  g_agg);
    cudaGetSymbolAddress((void**)&kv_p,   g_kv);
    cudaGetSymbolAddress((void**)&attp_p, g_attp);
    cudaGetSymbolAddress((void**)&xtp_p,  g_xtp);
    cudaGetSymbolAddress((void**)&wqp_p,  g_wqp);
    cudaGetSymbolAddress((void**)&wpp_p,  g_wpp);

    cudaFuncSetAttribute(gemm_fp16<16, false>,
                         cudaFuncAttributeMaxDynamicSharedMemorySize, GEMM_SMEM);
    cudaFuncSetAttribute(gemm_fp16<32, true>,
                         cudaFuncAttributeMaxDynamicSharedMemorySize, GEMM_SMEM);

    split_kernel<<<(OC_QKV * CIN + 255) / 256, 256>>>(w_qkv, wqp_p, OC_QKV, CIN, WSCALE);
    split_kernel<<<(OC_OUT * K_PROJ + 255) / 256, 256>>>(w_proj, wpp_p, OC_OUT, K_PROJ, WSCALE);
    {
        dim3 grid(HW / 32, CIN / 32, BATCH);
        transpose_kernel<<<grid, 256>>>(x, xtp_p);
    }
    // 1) qkv = W_qkv * x : fp16 3-term
    {
        dim3 grid(HW / 128, OC_QKV / 128, BATCH);
        gemm_fp16<16, false><<<grid, 256, GEMM_SMEM>>>(wqp_p, xtp_p, qkv_p, OC_QKV,
                                                       nullptr, nullptr, nullptr, nullptr);
    }
    // 2) depthwise + grouped pointwise
    {
        dim3 grid(4, 96, BATCH);
        dwpw_kernel<<<grid, 256>>>(qkv_p, w_dw, w_pw, agg_p);
    }
    // 3) kv partial reduction
    {
        dim3 grid(HEADS, BATCH, 4);
        kv_kernel<<<grid, 256>>>(qkv_p, agg_p, kv_p);
    }
    // 4) attention apply (paired fp16 att)
    {
        dim3 grid(HEADS, BATCH);
        apply_kernel<<<grid, 256>>>(qkv_p, agg_p, kv_p, attp_p);
    }
    // 5) y = W_proj * att + BN : fp16 3-term
    {
        dim3 grid(HW / 128, OC_OUT / 128, BATCH);
        gemm_fp16<32, true><<<grid, 256, GEMM_SMEM>>>(wpp_p, attp_p, out, OC_OUT,
                                                      gamma, beta, mean, var);
    }
}